// round 16
// baseline (speedup 1.0000x reference)
#include <cuda_runtime.h>
#include <cuda_fp16.h>
#include <cuda_bf16.h>
#include <cstdint>
#include <cstddef>

#define NE 256000
#define NN 16000
#define FEAT 60

// ---------------- device scratch ----------------
__device__ __align__(16) __nv_bfloat16 g_hidB[(size_t)NE * 64]; // hidden bf16 [e][k]
__device__ __align__(16) uint4 g_w1f[108 * 2 * 32];             // B frags [t][ks2][lane]
__device__ float g_shT[8 * NE];                                 // v(3), s2(5), [j][e]
__device__ __align__(16) float g_msg[NN * FEAT];

static __device__ __forceinline__ uint32_t smem_u32(const void* p) {
    uint32_t a;
    asm("{ .reg .u64 t; cvta.to.shared.u64 t, %1; cvt.u32.u64 %0, t; }" : "=r"(a) : "l"(p));
    return a;
}
static __device__ __forceinline__ void red_add_v4(float* p, float a, float b, float c, float d) {
    asm volatile("red.global.add.v4.f32 [%0], {%1,%2,%3,%4};"
                 :: "l"(p), "f"(a), "f"(b), "f"(c), "f"(d) : "memory");
}

// ---------------- K0: zero msg ----------------
__global__ void k0_zero() {
    int i = blockIdx.x * 256 + threadIdx.x;
    if (i < NN * FEAT) g_msg[i] = 0.0f;
}

// ---------------- K1: per-edge sh + hidden (bf16, row-major) ----------------
__global__ __launch_bounds__(256) void k1_prep(
    const float* __restrict__ pos, const float* __restrict__ ea,
    const float* __restrict__ W0, const int* __restrict__ esrc,
    const int* __restrict__ edst)
{
    __shared__ float W0s[512];
    int tid = threadIdx.x;
    for (int i = tid; i < 512; i += 256) W0s[i] = W0[i];
    __syncthreads();

    int e = blockIdx.x * 256 + tid;

    float a[8];
    const float4 v0_ = *(const float4*)&ea[(size_t)e * 8];
    const float4 v1_ = *(const float4*)&ea[(size_t)e * 8 + 4];
    a[0]=v0_.x; a[1]=v0_.y; a[2]=v0_.z; a[3]=v0_.w;
    a[4]=v1_.x; a[5]=v1_.y; a[6]=v1_.z; a[7]=v1_.w;

    __nv_bfloat16 hb[64];
    #pragma unroll
    for (int h = 0; h < 64; h++) {
        float acc = 0.f;
        #pragma unroll
        for (int j = 0; j < 8; j++) acc += a[j] * W0s[j * 64 + h];
        hb[h] = __float2bfloat16(0.5f * fmaxf(acc, 0.0f));
    }
    uint4* dst4 = (uint4*)&g_hidB[(size_t)e * 64];
    #pragma unroll
    for (int c = 0; c < 8; c++) dst4[c] = ((const uint4*)hb)[c];

    int s = esrc[e], d = edst[e];
    float vx = pos[d*3+0] - pos[s*3+0];
    float vy = pos[d*3+1] - pos[s*3+1];
    float vz = pos[d*3+2] - pos[s*3+2];
    float inv = rsqrtf(vx*vx + vy*vy + vz*vz + 1e-12f);
    float x = vx*inv, y = vy*inv, z = vz*inv;
    const float SQ5  = 2.2360679774997896f;
    const float SQ15 = 3.872983346207417f;
    g_shT[(size_t)0*NE + e] = x;
    g_shT[(size_t)1*NE + e] = y;
    g_shT[(size_t)2*NE + e] = z;
    g_shT[(size_t)3*NE + e] = SQ15 * x * z;
    g_shT[(size_t)4*NE + e] = SQ15 * x * y;
    g_shT[(size_t)5*NE + e] = SQ5 * (y*y - 0.5f*(x*x + z*z));
    g_shT[(size_t)6*NE + e] = SQ15 * y * z;
    g_shT[(size_t)7*NE + e] = 0.5f * SQ15 * (z*z - x*x);
}

// ---------------- K1b: pack W1 into mma B-fragment layout, scale 1/8 folded ----------------
__global__ void k1b_frag(const float* __restrict__ W1) {
    int i = blockIdx.x * 256 + threadIdx.x;
    if (i >= 108 * 2 * 32 * 4) return;
    int w    = i & 3;
    int lane = (i >> 2) & 31;
    int ks2  = (i >> 7) & 1;
    int t    = i >> 8;
    int ks   = ks2 * 2 + (w >> 1);
    int r    = w & 1;
    int n    = t * 8 + (lane >> 2);
    int k    = ks * 16 + (lane & 3) * 2 + r * 8;
    __nv_bfloat16 lo = __float2bfloat16(0.125f * W1[k * 864 + n]);
    __nv_bfloat16 hi = __float2bfloat16(0.125f * W1[(k + 1) * 864 + n]);
    uint32_t val = ((uint32_t)*(uint16_t*)&hi << 16) | *(uint16_t*)&lo;
    ((uint32_t*)g_w1f)[i] = val;
}

// ---------------- K23: fused GEMM + TP + scatter (128 edges, 512 thr, 1 CTA/SM) ----------------
// smem: sW [128][872] fp16 = 223232 B. GEMM: 16 warps = 4m x 4n, warp tile 32m x 24n/chunk.
// TP: warp w = subset (w&3), edge quarter (w>>2).
static __device__ __forceinline__ void mma_bf16(
    float* d, const uint32_t* a, const uint32_t* b)
{
    asm volatile(
        "mma.sync.aligned.m16n8k16.row.col.f32.bf16.bf16.f32 "
        "{%0,%1,%2,%3}, {%4,%5,%6,%7}, {%8,%9}, {%0,%1,%2,%3};"
        : "+f"(d[0]), "+f"(d[1]), "+f"(d[2]), "+f"(d[3])
        : "r"(a[0]), "r"(a[1]), "r"(a[2]), "r"(a[3]), "r"(b[0]), "r"(b[1]));
}
static __device__ __forceinline__ void ldsm_x4(
    uint32_t& r0, uint32_t& r1, uint32_t& r2, uint32_t& r3, uint32_t addr)
{
    asm volatile("ldmatrix.sync.aligned.m8n8.x4.shared.b16 {%0,%1,%2,%3}, [%4];"
                 : "=r"(r0), "=r"(r1), "=r"(r2), "=r"(r3) : "r"(addr));
}
static __device__ __forceinline__ uint32_t swz(uint32_t base, int row, int chunk) {
    return base + ((row << 3) + (chunk ^ (row & 7))) * 16;
}

#define SW_ROWH 872
#define K23_SMEM 223232

struct W8 { float2 p[4]; };
static __device__ __forceinline__ W8 ldw8s(const __half* sWp, int row, int cg) {
    uint4 q = *(const uint4*)(sWp + row * SW_ROWH + cg * 8);
    W8 w;
    w.p[0] = __half22float2(*(__half2*)&q.x);
    w.p[1] = __half22float2(*(__half2*)&q.y);
    w.p[2] = __half22float2(*(__half2*)&q.z);
    w.p[3] = __half22float2(*(__half2*)&q.w);
    return w;
}

__global__ __launch_bounds__(512) void k23_fused(
    const float* __restrict__ x, const int* __restrict__ esrc,
    const int* __restrict__ edst)
{
    extern __shared__ __align__(16) char smem_buf[];
    __half* sW = (__half*)smem_buf;
    __nv_bfloat16* sA = (__nv_bfloat16*)smem_buf;   // overlays sW (16 KB, used once)

    int tid  = threadIdx.x;
    int lane = tid & 31;
    int w    = tid >> 5;            // 0..15
    int wm   = w & 3;               // 0..3 along M (edges)
    int wn   = w >> 2;              // 0..3 along N
    int g    = lane >> 2;
    int tg   = lane & 3;
    int em0  = blockIdx.x * 128;

    uint32_t sa = smem_u32(sA);

    // ---- stage A (128 rows x 8 chunks = 1024 uint4) ----
    {
        const uint4* src = (const uint4*)&g_hidB[(size_t)em0 * 64];
        #pragma unroll
        for (int it = 0; it < 2; it++) {
            int idx = it * 512 + tid;
            int r = idx >> 3, c = idx & 7;
            *(uint4*)(sA + ((r << 3) + (c ^ (r & 7))) * 8) = src[idx];
        }
    }
    __syncthreads();

    // ---- A fragments persistent: 2 m16 tiles per warp ----
    int hi = lane >> 4;
    uint32_t afr[4][2][4];
    #pragma unroll
    for (int ks = 0; ks < 4; ks++)
        #pragma unroll
        for (int mt = 0; mt < 2; mt++)
            ldsm_x4(afr[ks][mt][0], afr[ks][mt][1], afr[ks][mt][2], afr[ks][mt][3],
                    swz(sa, wm * 32 + mt * 16 + (lane & 15), ks * 2 + hi));
    __syncthreads();   // all warps done reading sA before epilogue overwrites it

    // ---- GEMM: 9 chunks, warp tile 32m x 24n, no barriers ----
    for (int nc = 0; nc < 9; nc++) {
        float acc[2][3][4];
        #pragma unroll
        for (int mt = 0; mt < 2; mt++)
            #pragma unroll
            for (int nt = 0; nt < 3; nt++)
                #pragma unroll
                for (int i = 0; i < 4; i++) acc[mt][nt][i] = 0.f;

        #pragma unroll
        for (int nt = 0; nt < 3; nt++) {
            int t = nc * 12 + wn * 3 + nt;
            #pragma unroll
            for (int ks2 = 0; ks2 < 2; ks2++) {
                uint4 q = g_w1f[(t * 2 + ks2) * 32 + lane];
                uint32_t blo[2] = {q.x, q.y};
                uint32_t bhi2[2] = {q.z, q.w};
                mma_bf16(acc[0][nt], afr[2 * ks2][0],     blo);
                mma_bf16(acc[0][nt], afr[2 * ks2 + 1][0], bhi2);
                mma_bf16(acc[1][nt], afr[2 * ks2][1],     blo);
                mma_bf16(acc[1][nt], afr[2 * ks2 + 1][1], bhi2);
            }
        }

        // epilogue: acc -> sW
        #pragma unroll
        for (int mt = 0; mt < 2; mt++) {
            int e0 = wm * 32 + mt * 16 + g;
            #pragma unroll
            for (int nt = 0; nt < 3; nt++) {
                int cg = nc * 12 + wn * 3 + nt;
                *(__half2*)(sW + e0 * SW_ROWH + cg * 8 + tg * 2) =
                    __floats2half2_rn(acc[mt][nt][0], acc[mt][nt][1]);
                *(__half2*)(sW + (e0 + 8) * SW_ROWH + cg * 8 + tg * 2) =
                    __floats2half2_rn(acc[mt][nt][2], acc[mt][nt][3]);
            }
        }
    }
    __syncthreads();

    // ================= TP phase: warp w = subset (w&3), edges (w>>2)*32 + lane =================
    int q  = w & 3;
    int el = (w >> 2) * 32 + lane;
    int e  = em0 + el;
    int src = esrc[e], dst = edst[e];
    const float* xr = x + (size_t)src * FEAT;
    float* mb = g_msg + (size_t)dst * FEAT;

    if (q == 0) {
        float xs[16];
        #pragma unroll
        for (int p = 0; p < 4; p++) {
            float4 v = *(const float4*)&xr[p * 4];
            xs[p*4+0] = v.x; xs[p*4+1] = v.y; xs[p*4+2] = v.z; xs[p*4+3] = v.w;
        }
        float a0[16];
        #pragma unroll
        for (int i = 0; i < 16; i++) a0[i] = 0.f;
        #pragma unroll
        for (int u = 0; u < 16; u++) {
            float t = 0.18898223650461363f * xs[u];
            W8 wa = ldw8s(sW, el, 2*u), wb = ldw8s(sW, el, 2*u + 1);
            #pragma unroll
            for (int j = 0; j < 4; j++) {
                a0[2*j]   += t * wa.p[j].x;  a0[2*j+1] += t * wa.p[j].y;
                a0[8+2*j] += t * wb.p[j].x;  a0[9+2*j] += t * wb.p[j].y;
            }
        }
        #pragma unroll
        for (int p = 0; p < 4; p++)
            red_add_v4(mb + p * 4, a0[p*4+0], a0[p*4+1], a0[p*4+2], a0[p*4+3]);
    } else if (q == 1) {
        float v0 = g_shT[(size_t)0*NE + e];
        float v1 = g_shT[(size_t)1*NE + e];
        float v2 = g_shT[(size_t)2*NE + e];
        float s0 = g_shT[(size_t)3*NE + e];
        float s1 = g_shT[(size_t)4*NE + e];
        float s2 = g_shT[(size_t)5*NE + e];
        float s3 = g_shT[(size_t)6*NE + e];
        float s4 = g_shT[(size_t)7*NE + e];
        float xv[24];
        #pragma unroll
        for (int p = 0; p < 6; p++) {
            float4 v = *(const float4*)&xr[16 + p * 4];
            xv[p*4+0] = v.x; xv[p*4+1] = v.y; xv[p*4+2] = v.z; xv[p*4+3] = v.w;
        }
        float y[20];
        #pragma unroll
        for (int p = 0; p < 5; p++) {
            float4 v = *(const float4*)&xr[40 + p * 4];
            y[p*4+0] = v.x; y[p*4+1] = v.y; y[p*4+2] = v.z; y[p*4+3] = v.w;
        }
        float a0[16];
        #pragma unroll
        for (int i = 0; i < 16; i++) a0[i] = 0.f;
        #pragma unroll
        for (int u = 0; u < 8; u++) {
            float dv = 0.18898223650461363f *
                (xv[u*3+0]*v0 + xv[u*3+1]*v1 + xv[u*3+2]*v2);
            W8 wa = ldw8s(sW, el, 64 + 2*u), wb = ldw8s(sW, el, 65 + 2*u);
            #pragma unroll
            for (int j = 0; j < 4; j++) {
                a0[2*j]   += dv * wa.p[j].x;  a0[2*j+1] += dv * wa.p[j].y;
                a0[8+2*j] += dv * wb.p[j].x;  a0[9+2*j] += dv * wb.p[j].y;
            }
        }
        #pragma unroll
        for (int u = 0; u < 4; u++) {
            float dv = 0.08451542547285166f *
                (y[u*5+0]*s0 + y[u*5+1]*s1 + y[u*5+2]*s2 +
                 y[u*5+3]*s3 + y[u*5+4]*s4);
            W8 wa = ldw8s(sW, el, 98 + 2*u), wb = ldw8s(sW, el, 99 + 2*u);
            #pragma unroll
            for (int j = 0; j < 4; j++) {
                a0[2*j]   += dv * wa.p[j].x;  a0[2*j+1] += dv * wa.p[j].y;
                a0[8+2*j] += dv * wb.p[j].x;  a0[9+2*j] += dv * wb.p[j].y;
            }
        }
        #pragma unroll
        for (int p = 0; p < 4; p++)
            red_add_v4(mb + p * 4, a0[p*4+0], a0[p*4+1], a0[p*4+2], a0[p*4+3]);
    } else if (q == 2) {
        float v0 = g_shT[(size_t)0*NE + e];
        float v1 = g_shT[(size_t)1*NE + e];
        float v2 = g_shT[(size_t)2*NE + e];
        float s0 = g_shT[(size_t)3*NE + e];
        float s1 = g_shT[(size_t)4*NE + e];
        float s2 = g_shT[(size_t)5*NE + e];
        float s3 = g_shT[(size_t)6*NE + e];
        float s4 = g_shT[(size_t)7*NE + e];
        float xs[16];
        #pragma unroll
        for (int p = 0; p < 4; p++) {
            float4 v = *(const float4*)&xr[p * 4];
            xs[p*4+0] = v.x; xs[p*4+1] = v.y; xs[p*4+2] = v.z; xs[p*4+3] = v.w;
        }
        float xv[24];
        #pragma unroll
        for (int p = 0; p < 6; p++) {
            float4 v = *(const float4*)&xr[16 + p * 4];
            xv[p*4+0] = v.x; xv[p*4+1] = v.y; xv[p*4+2] = v.z; xv[p*4+3] = v.w;
        }
        float y[20];
        #pragma unroll
        for (int p = 0; p < 5; p++) {
            float4 v = *(const float4*)&xr[40 + p * 4];
            y[p*4+0] = v.x; y[p*4+1] = v.y; y[p*4+2] = v.z; y[p*4+3] = v.w;
        }
        float a1[24];
        #pragma unroll
        for (int i = 0; i < 24; i++) a1[i] = 0.f;
        {
            float d1[8];
            #pragma unroll
            for (int i = 0; i < 8; i++) d1[i] = 0.f;
            #pragma unroll
            for (int u = 0; u < 16; u++) {
                float xu = xs[u];
                W8 wv = ldw8s(sW, el, 32 + u);
                #pragma unroll
                for (int j = 0; j < 4; j++) {
                    d1[2*j]   += xu * wv.p[j].x;
                    d1[2*j+1] += xu * wv.p[j].y;
                }
            }
            const float c = 0.2886751345948129f;
            #pragma unroll
            for (int wo = 0; wo < 8; wo++) {
                float t = c * d1[wo];
                a1[wo*3+0] += t * v0;
                a1[wo*3+1] += t * v1;
                a1[wo*3+2] += t * v2;
            }
        }
        #pragma unroll
        for (int u = 0; u < 8; u++) {
            float t0 = 0.16666666666666666f * xv[u*3+0];
            float t1 = 0.16666666666666666f * xv[u*3+1];
            float t2 = 0.16666666666666666f * xv[u*3+2];
            W8 wv = ldw8s(sW, el, 56 + u);
            #pragma unroll
            for (int j = 0; j < 4; j++) {
                a1[(2*j)*3+0]   += t0 * wv.p[j].x;
                a1[(2*j)*3+1]   += t1 * wv.p[j].x;
                a1[(2*j)*3+2]   += t2 * wv.p[j].x;
                a1[(2*j+1)*3+0] += t0 * wv.p[j].y;
                a1[(2*j+1)*3+1] += t1 * wv.p[j].y;
                a1[(2*j+1)*3+2] += t2 * wv.p[j].y;
            }
        }
        #pragma unroll
        for (int u = 0; u < 8; u++) {
            const float aa = 0.09128709291752768f, bb = 0.05270462766947299f;
            float x0 = xv[u*3+0], x1 = xv[u*3+1], x2v = xv[u*3+2];
            float t0 = aa*(x1*s1 + x2v*s0 - x0*s4) - bb*x0*s2;
            float t1 = aa*(x0*s1 + x2v*s3) + 2.f*bb*x1*s2;
            float t2 = aa*(x0*s0 + x1*s3 + x2v*s4) - bb*x2v*s2;
            W8 wv = ldw8s(sW, el, 84 + u);
            #pragma unroll
            for (int j = 0; j < 4; j++) {
                a1[(2*j)*3+0]   += t0 * wv.p[j].x;
                a1[(2*j)*3+1]   += t1 * wv.p[j].x;
                a1[(2*j)*3+2]   += t2 * wv.p[j].x;
                a1[(2*j+1)*3+0] += t0 * wv.p[j].y;
                a1[(2*j+1)*3+1] += t1 * wv.p[j].y;
                a1[(2*j+1)*3+2] += t2 * wv.p[j].y;
            }
        }
        #pragma unroll
        for (int u = 0; u < 4; u++) {
            const float aa = 0.15811388300841897f, bb = 0.09128709291752768f;
            float y0 = y[u*5+0], y1 = y[u*5+1], y2 = y[u*5+2],
                  y3 = y[u*5+3], y4 = y[u*5+4];
            float t0 = aa*(v1*y1 + v2*y0 - v0*y4) - bb*v0*y2;
            float t1 = aa*(v0*y1 + v2*y3) + 2.f*bb*v1*y2;
            float t2 = aa*(v0*y0 + v1*y3 + v2*y4) - bb*v2*y2;
            W8 wv = ldw8s(sW, el, 94 + u);
            #pragma unroll
            for (int j = 0; j < 4; j++) {
                a1[(2*j)*3+0]   += t0 * wv.p[j].x;
                a1[(2*j)*3+1]   += t1 * wv.p[j].x;
                a1[(2*j)*3+2]   += t2 * wv.p[j].x;
                a1[(2*j+1)*3+0] += t0 * wv.p[j].y;
                a1[(2*j+1)*3+1] += t1 * wv.p[j].y;
                a1[(2*j+1)*3+2] += t2 * wv.p[j].y;
            }
        }
        #pragma unroll
        for (int p = 0; p < 6; p++)
            red_add_v4(mb + 16 + p * 4, a1[p*4+0], a1[p*4+1], a1[p*4+2], a1[p*4+3]);
    } else {
        float v0 = g_shT[(size_t)0*NE + e];
        float v1 = g_shT[(size_t)1*NE + e];
        float v2 = g_shT[(size_t)2*NE + e];
        float s0 = g_shT[(size_t)3*NE + e];
        float s1 = g_shT[(size_t)4*NE + e];
        float s2 = g_shT[(size_t)5*NE + e];
        float s3 = g_shT[(size_t)6*NE + e];
        float s4 = g_shT[(size_t)7*NE + e];
        float xs[16];
        #pragma unroll
        for (int p = 0; p < 4; p++) {
            float4 v = *(const float4*)&xr[p * 4];
            xs[p*4+0] = v.x; xs[p*4+1] = v.y; xs[p*4+2] = v.z; xs[p*4+3] = v.w;
        }
        float xv[24];
        #pragma unroll
        for (int p = 0; p < 6; p++) {
            float4 v = *(const float4*)&xr[16 + p * 4];
            xv[p*4+0] = v.x; xv[p*4+1] = v.y; xv[p*4+2] = v.z; xv[p*4+3] = v.w;
        }
        float y[20];
        #pragma unroll
        for (int p = 0; p < 5; p++) {
            float4 v = *(const float4*)&xr[40 + p * 4];
            y[p*4+0] = v.x; y[p*4+1] = v.y; y[p*4+2] = v.z; y[p*4+3] = v.w;
        }
        float a2[20];
        #pragma unroll
        for (int i = 0; i < 20; i++) a2[i] = 0.f;
        {
            float d2[4] = {0.f, 0.f, 0.f, 0.f};
            #pragma unroll
            for (int j2 = 0; j2 < 8; j2++) {
                W8 wv = ldw8s(sW, el, 48 + j2);
                float xa = xs[2*j2], xb = xs[2*j2+1];
                d2[0] += xa * wv.p[0].x + xb * wv.p[2].x;
                d2[1] += xa * wv.p[0].y + xb * wv.p[2].y;
                d2[2] += xa * wv.p[1].x + xb * wv.p[3].x;
                d2[3] += xa * wv.p[1].y + xb * wv.p[3].y;
            }
            const float c = 0.17677669529663687f;
            #pragma unroll
            for (int wo = 0; wo < 4; wo++) {
                float t = c * d2[wo];
                a2[wo*5+0] += t * s0; a2[wo*5+1] += t * s1; a2[wo*5+2] += t * s2;
                a2[wo*5+3] += t * s3; a2[wo*5+4] += t * s4;
            }
        }
        #pragma unroll
        for (int j2 = 0; j2 < 4; j2++) {
            const float A6 = 0.21650635094610965f, B6 = 0.125f;
            W8 wv = ldw8s(sW, el, 80 + j2);
            #pragma unroll
            for (int h = 0; h < 2; h++) {
                int u = 2*j2 + h;
                float x0 = xv[u*3+0], x1 = xv[u*3+1], x2v = xv[u*3+2];
                float t0 = A6 * (x0*v2 + x2v*v0);
                float t1 = A6 * (x0*v1 + x1*v0);
                float t2 = B6 * (2.f*x1*v1 - x0*v0 - x2v*v2);
                float t3 = A6 * (x1*v2 + x2v*v1);
                float t4 = A6 * (x2v*v2 - x0*v0);
                float2 pa = wv.p[2*h], pb = wv.p[2*h+1];
                a2[0*5+0] += t0 * pa.x; a2[0*5+1] += t1 * pa.x;
                a2[0*5+2] += t2 * pa.x; a2[0*5+3] += t3 * pa.x; a2[0*5+4] += t4 * pa.x;
                a2[1*5+0] += t0 * pa.y; a2[1*5+1] += t1 * pa.y;
                a2[1*5+2] += t2 * pa.y; a2[1*5+3] += t3 * pa.y; a2[1*5+4] += t4 * pa.y;
                a2[2*5+0] += t0 * pb.x; a2[2*5+1] += t1 * pb.x;
                a2[2*5+2] += t2 * pb.x; a2[2*5+3] += t3 * pb.x; a2[2*5+4] += t4 * pb.x;
                a2[3*5+0] += t0 * pb.y; a2[3*5+1] += t1 * pb.y;
                a2[3*5+2] += t2 * pb.y; a2[3*5+3] += t3 * pb.y; a2[3*5+4] += t4 * pb.y;
            }
        }
        #pragma unroll
        for (int j2 = 0; j2 < 2; j2++) {
            const float c = 0.17677669529663687f;
            W8 wv = ldw8s(sW, el, 92 + j2);
            #pragma unroll
            for (int h = 0; h < 2; h++) {
                int u = 2*j2 + h;
                float wx = c * wv.p[2*h].x, wy = c * wv.p[2*h].y;
                float wz = c * wv.p[2*h+1].x, ww = c * wv.p[2*h+1].y;
                #pragma unroll
                for (int k = 0; k < 5; k++) {
                    a2[0*5+k] += y[u*5+k] * wx;
                    a2[1*5+k] += y[u*5+k] * wy;
                    a2[2*5+k] += y[u*5+k] * wz;
                    a2[3*5+k] += y[u*5+k] * ww;
                }
            }
        }
        #pragma unroll
        for (int j2 = 0; j2 < 2; j2++) {
            const float G1 = 0.09449111825230679f;
            const float G2 = 0.047245559126153396f;
            const float G3 = 0.08183170883849714f;
            W8 wv = ldw8s(sW, el, 106 + j2);
            #pragma unroll
            for (int h = 0; h < 2; h++) {
                int u = 2*j2 + h;
                float y0 = y[u*5+0], y1 = y[u*5+1], y2 = y[u*5+2],
                      y3 = y[u*5+3], y4 = y[u*5+4];
                float t0 = G1*(y0*s2 + y2*s0) - G3*(y1*s3 + y3*s1);
                float t1 = -G2*(y1*s2 + y2*s1) + G3*(y1*s4 + y4*s1 - y0*s3 - y3*s0);
                float t2 = G1*(y0*s0 - y2*s2 + y4*s4) - G2*(y1*s1 + y3*s3);
                float t3 = -G2*(y3*s2 + y2*s3) - G3*(y3*s4 + y4*s3 + y0*s1 + y1*s0);
                float t4 = G1*(y4*s2 + y2*s4) + G3*(y1*s1 - y3*s3);
                float2 pa = wv.p[2*h], pb = wv.p[2*h+1];
                a2[0*5+0] += t0 * pa.x; a2[0*5+1] += t1 * pa.x;
                a2[0*5+2] += t2 * pa.x; a2[0*5+3] += t3 * pa.x; a2[0*5+4] += t4 * pa.x;
                a2[1*5+0] += t0 * pa.y; a2[1*5+1] += t1 * pa.y;
                a2[1*5+2] += t2 * pa.y; a2[1*5+3] += t3 * pa.y; a2[1*5+4] += t4 * pa.y;
                a2[2*5+0] += t0 * pb.x; a2[2*5+1] += t1 * pb.x;
                a2[2*5+2] += t2 * pb.x; a2[2*5+3] += t3 * pb.x; a2[2*5+4] += t4 * pb.x;
                a2[3*5+0] += t0 * pb.y; a2[3*5+1] += t1 * pb.y;
                a2[3*5+2] += t2 * pb.y; a2[3*5+3] += t3 * pb.y; a2[3*5+4] += t4 * pb.y;
            }
        }
        #pragma unroll
        for (int p = 0; p < 5; p++)
            red_add_v4(mb + 40 + p * 4, a2[p*4+0], a2[p*4+1], a2[p*4+2], a2[p*4+3]);
    }
}

// ---------------- K4: node update ----------------
__global__ __launch_bounds__(128) void k4_node(
    const float* __restrict__ x, const float* __restrict__ W0u,
    const float* __restrict__ W1u, const float* __restrict__ importance,
    float* __restrict__ out)
{
    __shared__ float W0s[32 * 64];
    __shared__ float W1s[64 * 16];
    int tid = threadIdx.x;
    for (int i = tid; i < 32 * 64; i += 128) W0s[i] = W0u[i];
    for (int i = tid; i < 64 * 16; i += 128) W1s[i] = W1u[i];
    __syncthreads();

    int n = blockIdx.x * 128 + tid;
    float sc = importance[0] * 0.25f;

    const float* xr = x + (size_t)n * FEAT;
    const float* mr = g_msg + (size_t)n * FEAT;

    float cat[32];
    #pragma unroll
    for (int i = 0; i < 16; i++) cat[i] = mr[i] * sc;
    #pragma unroll
    for (int i = 0; i < 16; i++) cat[16 + i] = xr[i];

    float h[64];
    #pragma unroll
    for (int j = 0; j < 64; j++) {
        float acc = 0.f;
        #pragma unroll
        for (int i = 0; i < 32; i++) acc += cat[i] * W0s[i * 64 + j];
        h[j] = 0.25f * fmaxf(acc, 0.f);
    }

    float* po = out + (size_t)n * FEAT;
    #pragma unroll
    for (int k = 0; k < 16; k++) {
        float acc = 0.f;
        #pragma unroll
        for (int j = 0; j < 64; j++) acc += h[j] * W1s[j * 16 + k];
        po[k] = 0.125f * acc;
    }
    #pragma unroll
    for (int f = 0; f < 44; f++)
        po[16 + f] = 0.5f * (mr[16 + f] * sc + xr[16 + f]);
}

// ---------------- launch ----------------
extern "C" void kernel_launch(void* const* d_in, const int* in_sizes, int n_in,
                              void* d_out, int out_size) {
    const float* x    = (const float*)d_in[0];
    const float* pos  = (const float*)d_in[1];
    const float* ea   = (const float*)d_in[2];
    const float* Wm0  = (const float*)d_in[3];
    const float* Wm1  = (const float*)d_in[4];
    const float* Wu0  = (const float*)d_in[5];
    const float* Wu1  = (const float*)d_in[6];
    const float* imp  = (const float*)d_in[7];
    const int*   esrc = (const int*)d_in[8];
    const int*   edst = (const int*)d_in[9];
    float* out = (float*)d_out;

    cudaFuncSetAttribute(k23_fused, cudaFuncAttributeMaxDynamicSharedMemorySize, K23_SMEM);

    k0_zero<<<(NN * FEAT + 255) / 256, 256>>>();
    k1_prep<<<NE / 256, 256>>>(pos, ea, Wm0, esrc, edst);
    k1b_frag<<<108, 256>>>(Wm1);
    k23_fused<<<NE / 128, 512, K23_SMEM>>>(x, esrc, edst);
    k4_node<<<NN / 128, 128>>>(x, Wu0, Wu1, imp, out);
}

// round 17
// speedup vs baseline: 1.0798x; 1.0798x over previous
#include <cuda_runtime.h>
#include <cuda_fp16.h>
#include <cuda_bf16.h>
#include <cstdint>
#include <cstddef>

#define NE 256000
#define NN 16000
#define FEAT 60

// ---------------- device scratch ----------------
__device__ __align__(16) uint4 g_w1f[108 * 2 * 32];             // B frags [t][ks2][lane]
__device__ float g_shT[8 * NE];                                 // v(3), s2(5), [j][e]
__device__ __align__(16) float g_msg[NN * FEAT];

static __device__ __forceinline__ uint32_t smem_u32(const void* p) {
    uint32_t a;
    asm("{ .reg .u64 t; cvta.to.shared.u64 t, %1; cvt.u32.u64 %0, t; }" : "=r"(a) : "l"(p));
    return a;
}
static __device__ __forceinline__ void red_add_v4(float* p, float a, float b, float c, float d) {
    asm volatile("red.global.add.v4.f32 [%0], {%1,%2,%3,%4};"
                 :: "l"(p), "f"(a), "f"(b), "f"(c), "f"(d) : "memory");
}

// ---------------- K0: zero msg ----------------
__global__ void k0_zero() {
    int i = blockIdx.x * 256 + threadIdx.x;
    if (i < NN * FEAT) g_msg[i] = 0.0f;
}

// ---------------- K1: per-edge spherical harmonics only ----------------
__global__ __launch_bounds__(256) void k1_sh(
    const float* __restrict__ pos, const int* __restrict__ esrc,
    const int* __restrict__ edst)
{
    int e = blockIdx.x * 256 + threadIdx.x;
    int s = esrc[e], d = edst[e];
    float vx = pos[d*3+0] - pos[s*3+0];
    float vy = pos[d*3+1] - pos[s*3+1];
    float vz = pos[d*3+2] - pos[s*3+2];
    float inv = rsqrtf(vx*vx + vy*vy + vz*vz + 1e-12f);
    float x = vx*inv, y = vy*inv, z = vz*inv;
    const float SQ5  = 2.2360679774997896f;
    const float SQ15 = 3.872983346207417f;
    g_shT[(size_t)0*NE + e] = x;
    g_shT[(size_t)1*NE + e] = y;
    g_shT[(size_t)2*NE + e] = z;
    g_shT[(size_t)3*NE + e] = SQ15 * x * z;
    g_shT[(size_t)4*NE + e] = SQ15 * x * y;
    g_shT[(size_t)5*NE + e] = SQ5 * (y*y - 0.5f*(x*x + z*z));
    g_shT[(size_t)6*NE + e] = SQ15 * y * z;
    g_shT[(size_t)7*NE + e] = 0.5f * SQ15 * (z*z - x*x);
}

// ---------------- K1b: pack W1 into mma B-fragment layout, scale 1/8 folded ----------------
__global__ void k1b_frag(const float* __restrict__ W1) {
    int i = blockIdx.x * 256 + threadIdx.x;
    if (i >= 108 * 2 * 32 * 4) return;
    int w    = i & 3;
    int lane = (i >> 2) & 31;
    int ks2  = (i >> 7) & 1;
    int t    = i >> 8;
    int ks   = ks2 * 2 + (w >> 1);
    int r    = w & 1;
    int n    = t * 8 + (lane >> 2);
    int k    = ks * 16 + (lane & 3) * 2 + r * 8;
    __nv_bfloat16 lo = __float2bfloat16(0.125f * W1[k * 864 + n]);
    __nv_bfloat16 hi = __float2bfloat16(0.125f * W1[(k + 1) * 864 + n]);
    uint32_t val = ((uint32_t)*(uint16_t*)&hi << 16) | *(uint16_t*)&lo;
    ((uint32_t*)g_w1f)[i] = val;
}

// ---------------- K23: fused edge-MLP + GEMM + TP + scatter (64 edges, 256 thr) ----------------
// smem: sW [64][872] fp16 = 111616 B (2 CTAs/SM). A-stage computes hidden in place from ea/W0.
// GEMM: 8 warps = 2m x 4n, warp tile 32m x 24n, 9 chunks, no barriers. TP: subset (w&3), half (w>>2).
static __device__ __forceinline__ void mma_bf16(
    float* d, const uint32_t* a, const uint32_t* b)
{
    asm volatile(
        "mma.sync.aligned.m16n8k16.row.col.f32.bf16.bf16.f32 "
        "{%0,%1,%2,%3}, {%4,%5,%6,%7}, {%8,%9}, {%0,%1,%2,%3};"
        : "+f"(d[0]), "+f"(d[1]), "+f"(d[2]), "+f"(d[3])
        : "r"(a[0]), "r"(a[1]), "r"(a[2]), "r"(a[3]), "r"(b[0]), "r"(b[1]));
}
static __device__ __forceinline__ void ldsm_x4(
    uint32_t& r0, uint32_t& r1, uint32_t& r2, uint32_t& r3, uint32_t addr)
{
    asm volatile("ldmatrix.sync.aligned.m8n8.x4.shared.b16 {%0,%1,%2,%3}, [%4];"
                 : "=r"(r0), "=r"(r1), "=r"(r2), "=r"(r3) : "r"(addr));
}
static __device__ __forceinline__ uint32_t swz(uint32_t base, int row, int chunk) {
    return base + ((row << 3) + (chunk ^ (row & 7))) * 16;
}

#define SW_ROWH 872
#define K23_SMEM 111616

struct W8 { float2 p[4]; };
static __device__ __forceinline__ W8 ldw8s(const __half* sWp, int row, int cg) {
    uint4 q = *(const uint4*)(sWp + row * SW_ROWH + cg * 8);
    W8 w;
    w.p[0] = __half22float2(*(__half2*)&q.x);
    w.p[1] = __half22float2(*(__half2*)&q.y);
    w.p[2] = __half22float2(*(__half2*)&q.z);
    w.p[3] = __half22float2(*(__half2*)&q.w);
    return w;
}

__global__ __launch_bounds__(256) void k23_fused(
    const float* __restrict__ x, const float* __restrict__ ea,
    const float* __restrict__ W0g, const int* __restrict__ esrc,
    const int* __restrict__ edst)
{
    extern __shared__ __align__(16) char smem_buf[];
    __half* sW = (__half*)smem_buf;
    __nv_bfloat16* sA = (__nv_bfloat16*)smem_buf;     // [0, 8192): A tile
    float* W0s = (float*)(smem_buf + 8192);           // [8192, 10240): W0, dead after A-stage

    int tid  = threadIdx.x;
    int lane = tid & 31;
    int w    = tid >> 5;            // 0..7
    int wm   = w & 1;
    int wn   = w >> 1;              // 0..3
    int g    = lane >> 2;
    int tg   = lane & 3;
    int em0  = blockIdx.x * 64;

    uint32_t sa = smem_u32(sA);

    // ---- stage W0 (8x64 floats) ----
    W0s[tid] = W0g[tid];
    W0s[tid + 256] = W0g[tid + 256];
    __syncthreads();

    // ---- A-stage: compute hidden = 0.5*relu(ea @ W0) in bf16, swizzled ----
    #pragma unroll
    for (int it = 0; it < 2; it++) {
        int idx = it * 256 + tid;         // 512 chunks: r=edge(0..63), c=chunk(0..7)
        int r = idx >> 3, c = idx & 7;
        const float4 e0 = *(const float4*)&ea[(size_t)(em0 + r) * 8];
        const float4 e1 = *(const float4*)&ea[(size_t)(em0 + r) * 8 + 4];
        float av[8] = {e0.x, e0.y, e0.z, e0.w, e1.x, e1.y, e1.z, e1.w};
        __nv_bfloat16 hb[8];
        #pragma unroll
        for (int jj = 0; jj < 8; jj++) {
            float acc = 0.f;
            #pragma unroll
            for (int j = 0; j < 8; j++) acc += av[j] * W0s[j * 64 + c * 8 + jj];
            hb[jj] = __float2bfloat16(0.5f * fmaxf(acc, 0.0f));
        }
        *(uint4*)(sA + ((r << 3) + (c ^ (r & 7))) * 8) = *(const uint4*)hb;
    }
    __syncthreads();

    // ---- A fragments persistent: 2 m16 tiles per warp ----
    int hi = lane >> 4;
    uint32_t afr[4][2][4];
    #pragma unroll
    for (int ks = 0; ks < 4; ks++)
        #pragma unroll
        for (int mt = 0; mt < 2; mt++)
            ldsm_x4(afr[ks][mt][0], afr[ks][mt][1], afr[ks][mt][2], afr[ks][mt][3],
                    swz(sa, wm * 32 + mt * 16 + (lane & 15), ks * 2 + hi));
    __syncthreads();   // all warps done reading sA before epilogue overwrites it

    // ---- GEMM: 9 chunks, warp tile 32m x 24n, no barriers ----
    for (int nc = 0; nc < 9; nc++) {
        float acc[2][3][4];
        #pragma unroll
        for (int mt = 0; mt < 2; mt++)
            #pragma unroll
            for (int nt = 0; nt < 3; nt++)
                #pragma unroll
                for (int i = 0; i < 4; i++) acc[mt][nt][i] = 0.f;

        #pragma unroll
        for (int nt = 0; nt < 3; nt++) {
            int t = nc * 12 + wn * 3 + nt;
            #pragma unroll
            for (int ks2 = 0; ks2 < 2; ks2++) {
                uint4 q = g_w1f[(t * 2 + ks2) * 32 + lane];
                uint32_t blo[2] = {q.x, q.y};
                uint32_t bhi2[2] = {q.z, q.w};
                mma_bf16(acc[0][nt], afr[2 * ks2][0],     blo);
                mma_bf16(acc[0][nt], afr[2 * ks2 + 1][0], bhi2);
                mma_bf16(acc[1][nt], afr[2 * ks2][1],     blo);
                mma_bf16(acc[1][nt], afr[2 * ks2 + 1][1], bhi2);
            }
        }

        // epilogue: acc -> sW
        #pragma unroll
        for (int mt = 0; mt < 2; mt++) {
            int e0 = wm * 32 + mt * 16 + g;
            #pragma unroll
            for (int nt = 0; nt < 3; nt++) {
                int cg = nc * 12 + wn * 3 + nt;
                *(__half2*)(sW + e0 * SW_ROWH + cg * 8 + tg * 2) =
                    __floats2half2_rn(acc[mt][nt][0], acc[mt][nt][1]);
                *(__half2*)(sW + (e0 + 8) * SW_ROWH + cg * 8 + tg * 2) =
                    __floats2half2_rn(acc[mt][nt][2], acc[mt][nt][3]);
            }
        }
    }
    __syncthreads();

    // ================= TP phase: warp w = subset (w&3), edges (w>>2)*32 + lane =================
    int q  = w & 3;
    int el = (w >> 2) * 32 + lane;
    int e  = em0 + el;
    int src = esrc[e], dst = edst[e];
    const float* xr = x + (size_t)src * FEAT;
    float* mb = g_msg + (size_t)dst * FEAT;

    if (q == 0) {
        float xs[16];
        #pragma unroll
        for (int p = 0; p < 4; p++) {
            float4 v = *(const float4*)&xr[p * 4];
            xs[p*4+0] = v.x; xs[p*4+1] = v.y; xs[p*4+2] = v.z; xs[p*4+3] = v.w;
        }
        float a0[16];
        #pragma unroll
        for (int i = 0; i < 16; i++) a0[i] = 0.f;
        #pragma unroll
        for (int u = 0; u < 16; u++) {
            float t = 0.18898223650461363f * xs[u];
            W8 wa = ldw8s(sW, el, 2*u), wb = ldw8s(sW, el, 2*u + 1);
            #pragma unroll
            for (int j = 0; j < 4; j++) {
                a0[2*j]   += t * wa.p[j].x;  a0[2*j+1] += t * wa.p[j].y;
                a0[8+2*j] += t * wb.p[j].x;  a0[9+2*j] += t * wb.p[j].y;
            }
        }
        #pragma unroll
        for (int p = 0; p < 4; p++)
            red_add_v4(mb + p * 4, a0[p*4+0], a0[p*4+1], a0[p*4+2], a0[p*4+3]);
    } else if (q == 1) {
        float v0 = g_shT[(size_t)0*NE + e];
        float v1 = g_shT[(size_t)1*NE + e];
        float v2 = g_shT[(size_t)2*NE + e];
        float s0 = g_shT[(size_t)3*NE + e];
        float s1 = g_shT[(size_t)4*NE + e];
        float s2 = g_shT[(size_t)5*NE + e];
        float s3 = g_shT[(size_t)6*NE + e];
        float s4 = g_shT[(size_t)7*NE + e];
        float xv[24];
        #pragma unroll
        for (int p = 0; p < 6; p++) {
            float4 v = *(const float4*)&xr[16 + p * 4];
            xv[p*4+0] = v.x; xv[p*4+1] = v.y; xv[p*4+2] = v.z; xv[p*4+3] = v.w;
        }
        float y[20];
        #pragma unroll
        for (int p = 0; p < 5; p++) {
            float4 v = *(const float4*)&xr[40 + p * 4];
            y[p*4+0] = v.x; y[p*4+1] = v.y; y[p*4+2] = v.z; y[p*4+3] = v.w;
        }
        float a0[16];
        #pragma unroll
        for (int i = 0; i < 16; i++) a0[i] = 0.f;
        #pragma unroll
        for (int u = 0; u < 8; u++) {
            float dv = 0.18898223650461363f *
                (xv[u*3+0]*v0 + xv[u*3+1]*v1 + xv[u*3+2]*v2);
            W8 wa = ldw8s(sW, el, 64 + 2*u), wb = ldw8s(sW, el, 65 + 2*u);
            #pragma unroll
            for (int j = 0; j < 4; j++) {
                a0[2*j]   += dv * wa.p[j].x;  a0[2*j+1] += dv * wa.p[j].y;
                a0[8+2*j] += dv * wb.p[j].x;  a0[9+2*j] += dv * wb.p[j].y;
            }
        }
        #pragma unroll
        for (int u = 0; u < 4; u++) {
            float dv = 0.08451542547285166f *
                (y[u*5+0]*s0 + y[u*5+1]*s1 + y[u*5+2]*s2 +
                 y[u*5+3]*s3 + y[u*5+4]*s4);
            W8 wa = ldw8s(sW, el, 98 + 2*u), wb = ldw8s(sW, el, 99 + 2*u);
            #pragma unroll
            for (int j = 0; j < 4; j++) {
                a0[2*j]   += dv * wa.p[j].x;  a0[2*j+1] += dv * wa.p[j].y;
                a0[8+2*j] += dv * wb.p[j].x;  a0[9+2*j] += dv * wb.p[j].y;
            }
        }
        #pragma unroll
        for (int p = 0; p < 4; p++)
            red_add_v4(mb + p * 4, a0[p*4+0], a0[p*4+1], a0[p*4+2], a0[p*4+3]);
    } else if (q == 2) {
        float v0 = g_shT[(size_t)0*NE + e];
        float v1 = g_shT[(size_t)1*NE + e];
        float v2 = g_shT[(size_t)2*NE + e];
        float s0 = g_shT[(size_t)3*NE + e];
        float s1 = g_shT[(size_t)4*NE + e];
        float s2 = g_shT[(size_t)5*NE + e];
        float s3 = g_shT[(size_t)6*NE + e];
        float s4 = g_shT[(size_t)7*NE + e];
        float xs[16];
        #pragma unroll
        for (int p = 0; p < 4; p++) {
            float4 v = *(const float4*)&xr[p * 4];
            xs[p*4+0] = v.x; xs[p*4+1] = v.y; xs[p*4+2] = v.z; xs[p*4+3] = v.w;
        }
        float xv[24];
        #pragma unroll
        for (int p = 0; p < 6; p++) {
            float4 v = *(const float4*)&xr[16 + p * 4];
            xv[p*4+0] = v.x; xv[p*4+1] = v.y; xv[p*4+2] = v.z; xv[p*4+3] = v.w;
        }
        float y[20];
        #pragma unroll
        for (int p = 0; p < 5; p++) {
            float4 v = *(const float4*)&xr[40 + p * 4];
            y[p*4+0] = v.x; y[p*4+1] = v.y; y[p*4+2] = v.z; y[p*4+3] = v.w;
        }
        float a1[24];
        #pragma unroll
        for (int i = 0; i < 24; i++) a1[i] = 0.f;
        {
            float d1[8];
            #pragma unroll
            for (int i = 0; i < 8; i++) d1[i] = 0.f;
            #pragma unroll
            for (int u = 0; u < 16; u++) {
                float xu = xs[u];
                W8 wv = ldw8s(sW, el, 32 + u);
                #pragma unroll
                for (int j = 0; j < 4; j++) {
                    d1[2*j]   += xu * wv.p[j].x;
                    d1[2*j+1] += xu * wv.p[j].y;
                }
            }
            const float c = 0.2886751345948129f;
            #pragma unroll
            for (int wo = 0; wo < 8; wo++) {
                float t = c * d1[wo];
                a1[wo*3+0] += t * v0;
                a1[wo*3+1] += t * v1;
                a1[wo*3+2] += t * v2;
            }
        }
        #pragma unroll
        for (int u = 0; u < 8; u++) {
            float t0 = 0.16666666666666666f * xv[u*3+0];
            float t1 = 0.16666666666666666f * xv[u*3+1];
            float t2 = 0.16666666666666666f * xv[u*3+2];
            W8 wv = ldw8s(sW, el, 56 + u);
            #pragma unroll
            for (int j = 0; j < 4; j++) {
                a1[(2*j)*3+0]   += t0 * wv.p[j].x;
                a1[(2*j)*3+1]   += t1 * wv.p[j].x;
                a1[(2*j)*3+2]   += t2 * wv.p[j].x;
                a1[(2*j+1)*3+0] += t0 * wv.p[j].y;
                a1[(2*j+1)*3+1] += t1 * wv.p[j].y;
                a1[(2*j+1)*3+2] += t2 * wv.p[j].y;
            }
        }
        #pragma unroll
        for (int u = 0; u < 8; u++) {
            const float aa = 0.09128709291752768f, bb = 0.05270462766947299f;
            float x0 = xv[u*3+0], x1 = xv[u*3+1], x2v = xv[u*3+2];
            float t0 = aa*(x1*s1 + x2v*s0 - x0*s4) - bb*x0*s2;
            float t1 = aa*(x0*s1 + x2v*s3) + 2.f*bb*x1*s2;
            float t2 = aa*(x0*s0 + x1*s3 + x2v*s4) - bb*x2v*s2;
            W8 wv = ldw8s(sW, el, 84 + u);
            #pragma unroll
            for (int j = 0; j < 4; j++) {
                a1[(2*j)*3+0]   += t0 * wv.p[j].x;
                a1[(2*j)*3+1]   += t1 * wv.p[j].x;
                a1[(2*j)*3+2]   += t2 * wv.p[j].x;
                a1[(2*j+1)*3+0] += t0 * wv.p[j].y;
                a1[(2*j+1)*3+1] += t1 * wv.p[j].y;
                a1[(2*j+1)*3+2] += t2 * wv.p[j].y;
            }
        }
        #pragma unroll
        for (int u = 0; u < 4; u++) {
            const float aa = 0.15811388300841897f, bb = 0.09128709291752768f;
            float y0 = y[u*5+0], y1 = y[u*5+1], y2 = y[u*5+2],
                  y3 = y[u*5+3], y4 = y[u*5+4];
            float t0 = aa*(v1*y1 + v2*y0 - v0*y4) - bb*v0*y2;
            float t1 = aa*(v0*y1 + v2*y3) + 2.f*bb*v1*y2;
            float t2 = aa*(v0*y0 + v1*y3 + v2*y4) - bb*v2*y2;
            W8 wv = ldw8s(sW, el, 94 + u);
            #pragma unroll
            for (int j = 0; j < 4; j++) {
                a1[(2*j)*3+0]   += t0 * wv.p[j].x;
                a1[(2*j)*3+1]   += t1 * wv.p[j].x;
                a1[(2*j)*3+2]   += t2 * wv.p[j].x;
                a1[(2*j+1)*3+0] += t0 * wv.p[j].y;
                a1[(2*j+1)*3+1] += t1 * wv.p[j].y;
                a1[(2*j+1)*3+2] += t2 * wv.p[j].y;
            }
        }
        #pragma unroll
        for (int p = 0; p < 6; p++)
            red_add_v4(mb + 16 + p * 4, a1[p*4+0], a1[p*4+1], a1[p*4+2], a1[p*4+3]);
    } else {
        float v0 = g_shT[(size_t)0*NE + e];
        float v1 = g_shT[(size_t)1*NE + e];
        float v2 = g_shT[(size_t)2*NE + e];
        float s0 = g_shT[(size_t)3*NE + e];
        float s1 = g_shT[(size_t)4*NE + e];
        float s2 = g_shT[(size_t)5*NE + e];
        float s3 = g_shT[(size_t)6*NE + e];
        float s4 = g_shT[(size_t)7*NE + e];
        float xs[16];
        #pragma unroll
        for (int p = 0; p < 4; p++) {
            float4 v = *(const float4*)&xr[p * 4];
            xs[p*4+0] = v.x; xs[p*4+1] = v.y; xs[p*4+2] = v.z; xs[p*4+3] = v.w;
        }
        float xv[24];
        #pragma unroll
        for (int p = 0; p < 6; p++) {
            float4 v = *(const float4*)&xr[16 + p * 4];
            xv[p*4+0] = v.x; xv[p*4+1] = v.y; xv[p*4+2] = v.z; xv[p*4+3] = v.w;
        }
        float y[20];
        #pragma unroll
        for (int p = 0; p < 5; p++) {
            float4 v = *(const float4*)&xr[40 + p * 4];
            y[p*4+0] = v.x; y[p*4+1] = v.y; y[p*4+2] = v.z; y[p*4+3] = v.w;
        }
        float a2[20];
        #pragma unroll
        for (int i = 0; i < 20; i++) a2[i] = 0.f;
        {
            float d2[4] = {0.f, 0.f, 0.f, 0.f};
            #pragma unroll
            for (int j2 = 0; j2 < 8; j2++) {
                W8 wv = ldw8s(sW, el, 48 + j2);
                float xa = xs[2*j2], xb = xs[2*j2+1];
                d2[0] += xa * wv.p[0].x + xb * wv.p[2].x;
                d2[1] += xa * wv.p[0].y + xb * wv.p[2].y;
                d2[2] += xa * wv.p[1].x + xb * wv.p[3].x;
                d2[3] += xa * wv.p[1].y + xb * wv.p[3].y;
            }
            const float c = 0.17677669529663687f;
            #pragma unroll
            for (int wo = 0; wo < 4; wo++) {
                float t = c * d2[wo];
                a2[wo*5+0] += t * s0; a2[wo*5+1] += t * s1; a2[wo*5+2] += t * s2;
                a2[wo*5+3] += t * s3; a2[wo*5+4] += t * s4;
            }
        }
        #pragma unroll
        for (int j2 = 0; j2 < 4; j2++) {
            const float A6 = 0.21650635094610965f, B6 = 0.125f;
            W8 wv = ldw8s(sW, el, 80 + j2);
            #pragma unroll
            for (int h = 0; h < 2; h++) {
                int u = 2*j2 + h;
                float x0 = xv[u*3+0], x1 = xv[u*3+1], x2v = xv[u*3+2];
                float t0 = A6 * (x0*v2 + x2v*v0);
                float t1 = A6 * (x0*v1 + x1*v0);
                float t2 = B6 * (2.f*x1*v1 - x0*v0 - x2v*v2);
                float t3 = A6 * (x1*v2 + x2v*v1);
                float t4 = A6 * (x2v*v2 - x0*v0);
                float2 pa = wv.p[2*h], pb = wv.p[2*h+1];
                a2[0*5+0] += t0 * pa.x; a2[0*5+1] += t1 * pa.x;
                a2[0*5+2] += t2 * pa.x; a2[0*5+3] += t3 * pa.x; a2[0*5+4] += t4 * pa.x;
                a2[1*5+0] += t0 * pa.y; a2[1*5+1] += t1 * pa.y;
                a2[1*5+2] += t2 * pa.y; a2[1*5+3] += t3 * pa.y; a2[1*5+4] += t4 * pa.y;
                a2[2*5+0] += t0 * pb.x; a2[2*5+1] += t1 * pb.x;
                a2[2*5+2] += t2 * pb.x; a2[2*5+3] += t3 * pb.x; a2[2*5+4] += t4 * pb.x;
                a2[3*5+0] += t0 * pb.y; a2[3*5+1] += t1 * pb.y;
                a2[3*5+2] += t2 * pb.y; a2[3*5+3] += t3 * pb.y; a2[3*5+4] += t4 * pb.y;
            }
        }
        #pragma unroll
        for (int j2 = 0; j2 < 2; j2++) {
            const float c = 0.17677669529663687f;
            W8 wv = ldw8s(sW, el, 92 + j2);
            #pragma unroll
            for (int h = 0; h < 2; h++) {
                int u = 2*j2 + h;
                float wx = c * wv.p[2*h].x, wy = c * wv.p[2*h].y;
                float wz = c * wv.p[2*h+1].x, ww = c * wv.p[2*h+1].y;
                #pragma unroll
                for (int k = 0; k < 5; k++) {
                    a2[0*5+k] += y[u*5+k] * wx;
                    a2[1*5+k] += y[u*5+k] * wy;
                    a2[2*5+k] += y[u*5+k] * wz;
                    a2[3*5+k] += y[u*5+k] * ww;
                }
            }
        }
        #pragma unroll
        for (int j2 = 0; j2 < 2; j2++) {
            const float G1 = 0.09449111825230679f;
            const float G2 = 0.047245559126153396f;
            const float G3 = 0.08183170883849714f;
            W8 wv = ldw8s(sW, el, 106 + j2);
            #pragma unroll
            for (int h = 0; h < 2; h++) {
                int u = 2*j2 + h;
                float y0 = y[u*5+0], y1 = y[u*5+1], y2 = y[u*5+2],
                      y3 = y[u*5+3], y4 = y[u*5+4];
                float t0 = G1*(y0*s2 + y2*s0) - G3*(y1*s3 + y3*s1);
                float t1 = -G2*(y1*s2 + y2*s1) + G3*(y1*s4 + y4*s1 - y0*s3 - y3*s0);
                float t2 = G1*(y0*s0 - y2*s2 + y4*s4) - G2*(y1*s1 + y3*s3);
                float t3 = -G2*(y3*s2 + y2*s3) - G3*(y3*s4 + y4*s3 + y0*s1 + y1*s0);
                float t4 = G1*(y4*s2 + y2*s4) + G3*(y1*s1 - y3*s3);
                float2 pa = wv.p[2*h], pb = wv.p[2*h+1];
                a2[0*5+0] += t0 * pa.x; a2[0*5+1] += t1 * pa.x;
                a2[0*5+2] += t2 * pa.x; a2[0*5+3] += t3 * pa.x; a2[0*5+4] += t4 * pa.x;
                a2[1*5+0] += t0 * pa.y; a2[1*5+1] += t1 * pa.y;
                a2[1*5+2] += t2 * pa.y; a2[1*5+3] += t3 * pa.y; a2[1*5+4] += t4 * pa.y;
                a2[2*5+0] += t0 * pb.x; a2[2*5+1] += t1 * pb.x;
                a2[2*5+2] += t2 * pb.x; a2[2*5+3] += t3 * pb.x; a2[2*5+4] += t4 * pb.x;
                a2[3*5+0] += t0 * pb.y; a2[3*5+1] += t1 * pb.y;
                a2[3*5+2] += t2 * pb.y; a2[3*5+3] += t3 * pb.y; a2[3*5+4] += t4 * pb.y;
            }
        }
        #pragma unroll
        for (int p = 0; p < 5; p++)
            red_add_v4(mb + 40 + p * 4, a2[p*4+0], a2[p*4+1], a2[p*4+2], a2[p*4+3]);
    }
}

// ---------------- K4: node update ----------------
__global__ __launch_bounds__(128) void k4_node(
    const float* __restrict__ x, const float* __restrict__ W0u,
    const float* __restrict__ W1u, const float* __restrict__ importance,
    float* __restrict__ out)
{
    __shared__ float W0s[32 * 64];
    __shared__ float W1s[64 * 16];
    int tid = threadIdx.x;
    for (int i = tid; i < 32 * 64; i += 128) W0s[i] = W0u[i];
    for (int i = tid; i < 64 * 16; i += 128) W1s[i] = W1u[i];
    __syncthreads();

    int n = blockIdx.x * 128 + tid;
    float sc = importance[0] * 0.25f;

    const float* xr = x + (size_t)n * FEAT;
    const float* mr = g_msg + (size_t)n * FEAT;

    float cat[32];
    #pragma unroll
    for (int i = 0; i < 16; i++) cat[i] = mr[i] * sc;
    #pragma unroll
    for (int i = 0; i < 16; i++) cat[16 + i] = xr[i];

    float h[64];
    #pragma unroll
    for (int j = 0; j < 64; j++) {
        float acc = 0.f;
        #pragma unroll
        for (int i = 0; i < 32; i++) acc += cat[i] * W0s[i * 64 + j];
        h[j] = 0.25f * fmaxf(acc, 0.f);
    }

    float* po = out + (size_t)n * FEAT;
    #pragma unroll
    for (int k = 0; k < 16; k++) {
        float acc = 0.f;
        #pragma unroll
        for (int j = 0; j < 64; j++) acc += h[j] * W1s[j * 16 + k];
        po[k] = 0.125f * acc;
    }
    #pragma unroll
    for (int f = 0; f < 44; f++)
        po[16 + f] = 0.5f * (mr[16 + f] * sc + xr[16 + f]);
}

// ---------------- launch ----------------
extern "C" void kernel_launch(void* const* d_in, const int* in_sizes, int n_in,
                              void* d_out, int out_size) {
    const float* x    = (const float*)d_in[0];
    const float* pos  = (const float*)d_in[1];
    const float* ea   = (const float*)d_in[2];
    const float* Wm0  = (const float*)d_in[3];
    const float* Wm1  = (const float*)d_in[4];
    const float* Wu0  = (const float*)d_in[5];
    const float* Wu1  = (const float*)d_in[6];
    const float* imp  = (const float*)d_in[7];
    const int*   esrc = (const int*)d_in[8];
    const int*   edst = (const int*)d_in[9];
    float* out = (float*)d_out;

    cudaFuncSetAttribute(k23_fused, cudaFuncAttributeMaxDynamicSharedMemorySize, K23_SMEM);

    k0_zero<<<(NN * FEAT + 255) / 256, 256>>>();
    k1_sh<<<NE / 256, 256>>>(pos, esrc, edst);
    k1b_frag<<<108, 256>>>(Wm1);
    k23_fused<<<NE / 64, 256, K23_SMEM>>>(x, ea, Wm0, esrc, edst);
    k4_node<<<NN / 128, 128>>>(x, Wu0, Wu1, imp, out);
}